// round 16
// baseline (speedup 1.0000x reference)
#include <cuda_runtime.h>
#include <cuda_bf16.h>
#include <math.h>

// ---------------- problem constants ----------------
#define N_LANG   64
#define N_EX     4
#define N_IMG    (N_LANG * N_EX)        // 256
#define M_REG    49
#define L_TOK    32
#define HDIM     512
#define MP1      (M_REG + 1)            // 50
#define LP1      (L_TOK + 1)            // 33
#define NB       (N_IMG * N_LANG)       // 16384 batch items
#define XROWS    (N_IMG * M_REG)        // 12544
#define YROWS    (N_LANG * L_TOK)       // 2048
#define REG      0.1f
#define INVREG   10.0f
#define TEMP     0.1f
#define ITERS    10
#define NEGV     (-1.0e7f)              // sentinel (exp2 -> 0)
#define LOG2E    1.4426950408889634f
#define LN2      0.6931471805599453f

// scratch (static device allocations are the sanctioned workaround)
__device__ float g_xn[(size_t)XROWS * HDIM];      // 25.7 MB
__device__ float g_yn[(size_t)YROWS * HDIM];      //  4.2 MB
__device__ float g_scores[(size_t)XROWS * YROWS]; // 102.8 MB
__device__ float g_ot[NB];
__device__ unsigned char g_mask[YROWS];

__device__ __forceinline__ float ex2f(float x) {
    float r; asm("ex2.approx.ftz.f32 %0, %1;" : "=f"(r) : "f"(x)); return r;
}
__device__ __forceinline__ float rcpf(float x) {
    float r; asm("rcp.approx.ftz.f32 %0, %1;" : "=f"(r) : "f"(x)); return r;
}

// ---------------- 0) decode y_mask regardless of storage dtype ----------------
__global__ void decode_mask_kernel(const void* __restrict__ p) {
    __shared__ int bad;
    if (threadIdx.x == 0) bad = 0;
    __syncthreads();
    const int* ip = (const int*)p;
    for (int k = threadIdx.x; k < 512; k += blockDim.x) {
        int w = ip[k];
        if (w != 0 && w != 1 && w != 0x3f800000) atomicOr(&bad, 1);
    }
    __syncthreads();
    if (bad) {  // byte-encoded mask
        const unsigned char* bp = (const unsigned char*)p;
        for (int k = threadIdx.x; k < YROWS; k += blockDim.x)
            g_mask[k] = bp[k] ? 1 : 0;
    } else {    // 4-byte-encoded mask (int32 0/1 or float32 0.0/1.0)
        for (int k = threadIdx.x; k < YROWS; k += blockDim.x)
            g_mask[k] = ip[k] ? 1 : 0;
    }
}

// ---------------- 1) L2 normalize rows of x and y ----------------
__global__ void norm_kernel(const float* __restrict__ x, const float* __restrict__ y) {
    int row  = (blockIdx.x * blockDim.x + threadIdx.x) >> 5;
    int lane = threadIdx.x & 31;
    if (row >= XROWS + YROWS) return;
    const float* src;
    float* dst;
    if (row < XROWS) { src = x + (size_t)row * HDIM;           dst = g_xn + (size_t)row * HDIM; }
    else             { src = y + (size_t)(row - XROWS) * HDIM; dst = g_yn + (size_t)(row - XROWS) * HDIM; }

    const float4* s4 = (const float4*)src;
    float4 v[4];
    float ss = 0.f;
#pragma unroll
    for (int q = 0; q < 4; q++) {
        v[q] = s4[lane + 32 * q];
        ss += v[q].x * v[q].x + v[q].y * v[q].y + v[q].z * v[q].z + v[q].w * v[q].w;
    }
#pragma unroll
    for (int o = 16; o; o >>= 1) ss += __shfl_xor_sync(0xffffffffu, ss, o);
    float inv = 1.0f / fmaxf(sqrtf(ss), 1e-12f);
    float4* d4 = (float4*)dst;
#pragma unroll
    for (int q = 0; q < 4; q++) {
        float4 w = v[q];
        w.x *= inv; w.y *= inv; w.z *= inv; w.w *= inv;
        d4[lane + 32 * q] = w;
    }
}

// ---------------- 2) scores GEMM: C[12544,2048] = Xn (12544x512) * Yn^T ----
// 128x128x16, 256 threads, 8x8 micro-tile, fma.rn.f32x2.
// v2: A stored PRE-DUPLICATED in smem (8B (a,a) pairs) -> no per-k packs,
//     A reads are broadcast LDS.128. Double-buffered smem -> 1 barrier/tile.
// (tcgen05 unavailable: harness lowers PTX at compute_103 — verified R12.)
#define BM 128
#define BN 128
#define BK 16

__device__ __forceinline__ unsigned long long pack_dup(float x) {
    unsigned long long r;
    asm("mov.b64 %0, {%1, %1};" : "=l"(r) : "f"(x));
    return r;
}
__device__ __forceinline__ void ffma2(unsigned long long& d, unsigned long long a,
                                      unsigned long long b) {
    asm("fma.rn.f32x2 %0, %1, %2, %0;" : "+l"(d) : "l"(a), "l"(b));
}

__global__ __launch_bounds__(256, 2) void gemm_kernel() {
    __shared__ unsigned long long As2[2][BK][128];   // 32 KB (duplicated pairs)
    __shared__ float Bs[2][BK][128];                 // 16 KB
    const int tid = threadIdx.x;
    const int m0 = blockIdx.y * BM;
    const int n0 = blockIdx.x * BN;

    const int lrow = tid >> 1;            // 0..127
    const int kb   = (tid & 1) * 8;       // 0 or 8
    const int ty   = tid >> 4;            // 0..15 -> row group
    const int tx   = tid & 15;            // 0..15 -> col pairs

    const float* Aptr = g_xn + (size_t)(m0 + lrow) * HDIM + kb;
    const float* Bptr = g_yn + (size_t)(n0 + lrow) * HDIM + kb;

    unsigned long long acc[8][4];
#pragma unroll
    for (int r = 0; r < 8; r++)
#pragma unroll
        for (int g = 0; g < 4; g++) acc[r][g] = 0ULL;

    float4 af0, af1, bf0, bf1;
    // prologue: tile 0 -> regs -> smem[0]
    af0 = *(const float4*)Aptr;       af1 = *(const float4*)(Aptr + 4);
    bf0 = *(const float4*)Bptr;       bf1 = *(const float4*)(Bptr + 4);
    {
        As2[0][kb + 0][lrow] = pack_dup(af0.x);
        As2[0][kb + 1][lrow] = pack_dup(af0.y);
        As2[0][kb + 2][lrow] = pack_dup(af0.z);
        As2[0][kb + 3][lrow] = pack_dup(af0.w);
        As2[0][kb + 4][lrow] = pack_dup(af1.x);
        As2[0][kb + 5][lrow] = pack_dup(af1.y);
        As2[0][kb + 6][lrow] = pack_dup(af1.z);
        As2[0][kb + 7][lrow] = pack_dup(af1.w);
        Bs[0][kb + 0][lrow] = bf0.x;  Bs[0][kb + 1][lrow] = bf0.y;
        Bs[0][kb + 2][lrow] = bf0.z;  Bs[0][kb + 3][lrow] = bf0.w;
        Bs[0][kb + 4][lrow] = bf1.x;  Bs[0][kb + 5][lrow] = bf1.y;
        Bs[0][kb + 6][lrow] = bf1.z;  Bs[0][kb + 7][lrow] = bf1.w;
    }
    __syncthreads();
    // prefetch tile 1
    af0 = *(const float4*)(Aptr + BK);     af1 = *(const float4*)(Aptr + BK + 4);
    bf0 = *(const float4*)(Bptr + BK);     bf1 = *(const float4*)(Bptr + BK + 4);

    const int NT = HDIM / BK;   // 32
    for (int kt = 0; kt < NT; kt++) {
        const int cur = kt & 1;
#pragma unroll
        for (int k = 0; k < BK; k++) {
            const unsigned long long* arow = &As2[cur][k][ty * 8];
            ulonglong2 a01 = *(const ulonglong2*)(arow + 0);
            ulonglong2 a23 = *(const ulonglong2*)(arow + 2);
            ulonglong2 a45 = *(const ulonglong2*)(arow + 4);
            ulonglong2 a67 = *(const ulonglong2*)(arow + 6);
            const float* brow = Bs[cur][k];
            unsigned long long b0 = *(const unsigned long long*)(brow + tx * 2);
            unsigned long long b1 = *(const unsigned long long*)(brow + 32 + tx * 2);
            unsigned long long b2 = *(const unsigned long long*)(brow + 64 + tx * 2);
            unsigned long long b3 = *(const unsigned long long*)(brow + 96 + tx * 2);
            unsigned long long ar[8] = {a01.x, a01.y, a23.x, a23.y,
                                        a45.x, a45.y, a67.x, a67.y};
#pragma unroll
            for (int r = 0; r < 8; r++) {
                ffma2(acc[r][0], ar[r], b0);
                ffma2(acc[r][1], ar[r], b1);
                ffma2(acc[r][2], ar[r], b2);
                ffma2(acc[r][3], ar[r], b3);
            }
        }
        if (kt + 1 < NT) {
            const int nxt = (kt + 1) & 1;
            As2[nxt][kb + 0][lrow] = pack_dup(af0.x);
            As2[nxt][kb + 1][lrow] = pack_dup(af0.y);
            As2[nxt][kb + 2][lrow] = pack_dup(af0.z);
            As2[nxt][kb + 3][lrow] = pack_dup(af0.w);
            As2[nxt][kb + 4][lrow] = pack_dup(af1.x);
            As2[nxt][kb + 5][lrow] = pack_dup(af1.y);
            As2[nxt][kb + 6][lrow] = pack_dup(af1.z);
            As2[nxt][kb + 7][lrow] = pack_dup(af1.w);
            Bs[nxt][kb + 0][lrow] = bf0.x;  Bs[nxt][kb + 1][lrow] = bf0.y;
            Bs[nxt][kb + 2][lrow] = bf0.z;  Bs[nxt][kb + 3][lrow] = bf0.w;
            Bs[nxt][kb + 4][lrow] = bf1.x;  Bs[nxt][kb + 5][lrow] = bf1.y;
            Bs[nxt][kb + 6][lrow] = bf1.z;  Bs[nxt][kb + 7][lrow] = bf1.w;
            __syncthreads();
            if (kt + 2 < NT) {
                const float* an = Aptr + (size_t)(kt + 2) * BK;
                const float* bn = Bptr + (size_t)(kt + 2) * BK;
                af0 = *(const float4*)an; af1 = *(const float4*)(an + 4);
                bf0 = *(const float4*)bn; bf1 = *(const float4*)(bn + 4);
            }
        }
    }

#pragma unroll
    for (int r = 0; r < 8; r++) {
        float* crow = &g_scores[(size_t)(m0 + ty * 8 + r) * YROWS + n0];
#pragma unroll
        for (int g = 0; g < 4; g++) {
            *(unsigned long long*)(crow + g * 32 + tx * 2) = acc[r][g];
        }
    }
}

// ---------------- 3) per-pair Sinkhorn (exp-domain, low-register) ----------
// Measured R14: 182.6 us, regs=32, occ=79.5%, L1=84.4% -> smem-wavefront
// bound at ~3400 wavefronts/CTA. Left unchanged this round.
__global__ __launch_bounds__(64) void sinkhorn_kernel(const float* __restrict__ dbim,
                                                      const float* __restrict__ dblang,
                                                      float* __restrict__ out_match) {
    __shared__ float E[MP1 * LP1];
    __shared__ float eu[MP1];
    __shared__ float ev[LP1];
    __shared__ unsigned char mc[LP1];
    __shared__ float sh_ns;
    __shared__ float wsum[2];

    const int bi = blockIdx.x;
    const int i = bi >> 6;       // image 0..255
    const int j = bi & 63;       // lang  0..63
    const int tid = threadIdx.x; // 64 threads

    if (tid < L_TOK) mc[tid] = g_mask[j * L_TOK + tid];
    if (tid == L_TOK) mc[L_TOK] = 0;
    __syncthreads();
    if (tid == 0) {
        int valid = 0;
        for (int c = 0; c < L_TOK; c++) valid += mc[c] ? 0 : 1;
        sh_ns = (float)valid;
    }

    const float a_im   = fminf(fmaxf(dbim[0],   -1.f), 1.f);
    const float a_lang = fminf(fmaxf(dblang[0], -1.f), 1.f);
    const float SC    = INVREG * LOG2E;   // score -> base-2 scaled
    const float binc2 = a_im   * SC;      // col 32 (all rows incl. corner)
    const float binr2 = a_lang * SC;      // row 49, cols < 32

    // build E = exp2(Z2) in smem (masked cols -> exp2(NEGV) = 0)
    const float* sbase = g_scores + (size_t)i * M_REG * YROWS + (size_t)j * L_TOK;
    {
        int r = tid / LP1, c = tid - r * LP1;
        for (int idx = tid; idx < MP1 * LP1; idx += 64) {
            float val;
            if (c < L_TOK) {
                if (mc[c])          val = NEGV;
                else if (r < M_REG) val = sbase[(size_t)r * YROWS + c] * SC;
                else                val = binr2;
            } else {
                val = binc2;
            }
            E[idx] = ex2f(val);
            r += 1; c += 31;
            if (c >= LP1) { c -= LP1; r += 1; }
        }
    }
    if (tid < LP1) ev[tid] = (tid < L_TOK && mc[tid]) ? 0.f : 1.f;
    __syncthreads();

    const bool colActive = (tid < LP1) && !(tid < L_TOK && mc[tid]);

    const float ns = sh_ns;
    const float tot = (float)M_REG + ns;                 // m + ns
    const float mu_v  = (tid < M_REG) ? 1.f : ns;
    const float nu_v  = (tid < L_TOK) ? 1.f : (float)M_REG;
    const float invtot = rcpf(tot);
    const float mu  = mu_v * invtot;
    const float nu  = nu_v * invtot;

    for (int it = 0; it < ITERS; it++) {
        // row pass: eu[r] = mu / sum_c E[r][c]*ev[c]
        if (tid < MP1) {
            const float* er = &E[tid * LP1];
            float s = 0.f;
#pragma unroll
            for (int c = 0; c < LP1; c++) s += er[c] * ev[c];
            eu[tid] = mu * rcpf(s);
        }
        __syncthreads();
        // col pass: ev[c] = nu / sum_r E[r][c]*eu[r]   (masked cols stay 0)
        if (colActive) {
            float s = 0.f;
#pragma unroll
            for (int r = 0; r < MP1; r++) s += E[r * LP1 + tid] * eu[r];
            ev[tid] = nu * rcpf(s);
        }
        __syncthreads();
    }

    // finalize: Zm = E*eu*ev*(m+ns); match output + ot partial
    // log-score recovered as log2(E) (E >= 2^-14.5 for unmasked entries).
    float part = 0.f;
    {
        int r = tid / LP1, c = tid - r * LP1;
        for (int idx = tid; idx < MP1 * LP1; idx += 64) {
            float e = E[idx];
            float zm = e * eu[r] * ev[c] * tot;
            if (out_match) out_match[(size_t)bi * (MP1 * LP1) + idx] = zm;
            if (r < M_REG && c < L_TOK && zm > 0.f) part += __log2f(e) * zm;
            r += 1; c += 31;
            if (c >= LP1) { c -= LP1; r += 1; }
        }
    }
#pragma unroll
    for (int o = 16; o; o >>= 1) part += __shfl_down_sync(0xffffffffu, part, o);
    if ((tid & 31) == 0) wsum[tid >> 5] = part;
    __syncthreads();
    // ot = sum(score*zm)/TEMP = part * (REG*LN2) / TEMP = part * LN2
    if (tid == 0) g_ot[bi] = (wsum[0] + wsum[1]) * LN2;
}

// ---------------- 4) InfoNCE loss over ot_scores (256x64) ----------------
__global__ __launch_bounds__(256) void loss_kernel(float* __restrict__ out_loss) {
    __shared__ float sl[8], si[8];
    const int i = threadIdx.x;        // image index 0..255
    const int grp = i >> 2;           // lang of image i
    const float* row = g_ot + i * N_LANG;
    const float pos = row[grp];

    float mx = -INFINITY;
    for (int c = 0; c < N_LANG; c++) mx = fmaxf(mx, row[c]);
    float s = 0.f;
    for (int c = 0; c < N_LANG; c++) s += __expf(row[c] - mx);
    float t_lang = pos - (mx + __logf(s));

    float mx2 = -INFINITY;
    for (int k = 0; k < N_IMG; k++) {
        if (((k >> 2) != grp) || (k == i)) mx2 = fmaxf(mx2, g_ot[k * N_LANG + grp]);
    }
    float s2 = 0.f;
    for (int k = 0; k < N_IMG; k++) {
        if (((k >> 2) != grp) || (k == i)) s2 += __expf(g_ot[k * N_LANG + grp] - mx2);
    }
    float t_im = pos - (mx2 + __logf(s2));

#pragma unroll
    for (int o = 16; o; o >>= 1) {
        t_lang += __shfl_down_sync(0xffffffffu, t_lang, o);
        t_im   += __shfl_down_sync(0xffffffffu, t_im, o);
    }
    if ((i & 31) == 0) { sl[i >> 5] = t_lang; si[i >> 5] = t_im; }
    __syncthreads();
    if (i == 0) {
        float a = 0.f, b = 0.f;
        for (int w = 0; w < 8; w++) { a += sl[w]; b += si[w]; }
        *out_loss = -0.5f * (a + b) / (float)N_IMG;
    }
}

// ---------------- launcher ----------------
extern "C" void kernel_launch(void* const* d_in, const int* in_sizes, int n_in,
                              void* d_out, int out_size) {
    const float* x      = (const float*)d_in[0];
    const float* y      = (const float*)d_in[1];
    const float* dbim   = (const float*)d_in[2];
    const float* dblang = (const float*)d_in[3];
    const void*  ymask  = d_in[4];

    float* outF = (float*)d_out;
    const long long MATCH = (long long)NB * MP1 * LP1;   // 27,033,600
    float* matchPtr = outF;
    float* lossPtr;
    if ((long long)out_size >= MATCH + 1) lossPtr = outF + MATCH;
    else if (out_size == 1)               { lossPtr = outF; matchPtr = nullptr; }
    else                                   lossPtr = outF;

    decode_mask_kernel<<<1, 256>>>(ymask);
    {   // normalize
        int rows = XROWS + YROWS;
        int blocks = (rows * 32 + 255) / 256;
        norm_kernel<<<blocks, 256>>>(x, y);
    }
    {   // GEMM: 12544/128 = 98, 2048/128 = 16
        dim3 grid(YROWS / BN, XROWS / BM);
        gemm_kernel<<<grid, 256>>>();
    }
    sinkhorn_kernel<<<NB, 64>>>(dbim, dblang, matchPtr);
    loss_kernel<<<1, 256>>>(lossPtr);
}